// round 10
// baseline (speedup 1.0000x reference)
#include <cuda_runtime.h>
#include <cuda_bf16.h>
#include <math.h>

// ---------------------------------------------------------------------------
// NodeSelfAtten: B=4, N=4096, F=512, C=64
//   out = gamma * softmax( relu(V Wf+bf) relu(V Wg+bg)^T ) relu(V Wh+bh) + V
// Round 10: holding the audited design (10th broker timeout; still no data).
// fp32-exact; all GEMM inner loops use packed fma.rn.f32x2 (FFMA2): 2 IEEE
// fp32 MACs per issue slot. Probabilities stored pre-splatted ({p,p} u64);
// GEMM2 branch-free with padded prefetch and 4-row JIT chunks (reg-capped);
// all three projections in ONE launch.
// ---------------------------------------------------------------------------

#define BDIM   4
#define NDIM   4096
#define FDIM   512
#define CDIM   64
#define MROWS  (BDIM * NDIM)        // 16384
#define LOG2E  1.4426950408889634f

typedef unsigned long long u64t;

__device__ __forceinline__ u64t ffma2(u64t a, u64t b, u64t c) {
    u64t d;
    asm("fma.rn.f32x2 %0, %1, %2, %3;" : "=l"(d) : "l"(a), "l"(b), "l"(c));
    return d;
}
__device__ __forceinline__ u64t fmul2(u64t a, u64t b) {
    u64t d;
    asm("mul.rn.f32x2 %0, %1, %2;" : "=l"(d) : "l"(a), "l"(b));
    return d;
}
__device__ __forceinline__ u64t splat2(float x) {
    u64t d;
    asm("mov.b64 %0, {%1, %1};" : "=l"(d) : "f"(x));
    return d;
}
__device__ __forceinline__ float2 unpack2(u64t v) {
    float lo, hi;
    asm("mov.b64 {%0, %1}, %2;" : "=f"(lo), "=f"(hi) : "l"(v));
    return make_float2(lo, hi);
}

// Scratch (device globals: allocation-free per harness rules).
// g_h padded +1024 floats so the GEMM2 prefetch of row j+1 is always legal.
__device__ float g_f[BDIM * NDIM * CDIM];          // 4 MB
__device__ float g_g[BDIM * NDIM * CDIM];          // 4 MB
__device__ float g_h[BDIM * NDIM * FDIM + 1024];   // 32 MB + pad

// ---------------------------------------------------------------------------
// Projection GEMM body: C[m,n] = relu( sum_k A[m,k] W[k,n] + bias[n] )
// BM=128, BN=64, BK=16, 256 threads, 8x4 micro-tile, packed-f32x2 inner loop.
// ---------------------------------------------------------------------------
__device__ __forceinline__
void proj_body(const float* __restrict__ A, const float* __restrict__ W,
               const float* __restrict__ bias, float* __restrict__ Cout,
               int Ncols, int row0, int col0)
{
    __shared__ float As[16][132];   // [k][row], padded
    __shared__ float Bs[16][68];    // [k][col], padded (272B stride)

    const int tid = threadIdx.x;
    const int rg  = tid >> 4;       // rows rg*8..rg*8+7
    const int cg  = tid & 15;       // cols cg*4..cg*4+3

    u64t acc2[8][2];                // pairs of columns {c,c+1}
    #pragma unroll
    for (int i = 0; i < 8; ++i) { acc2[i][0] = 0ull; acc2[i][1] = 0ull; }

    for (int kb = 0; kb < 512; kb += 16) {
        __syncthreads();
        #pragma unroll
        for (int t = 0; t < 2; ++t) {
            int s  = tid + t * 256;
            int r  = s >> 2;
            int kq = s & 3;
            float4 v = *(const float4*)(A + (size_t)(row0 + r) * 512 + kb + kq * 4);
            As[kq * 4 + 0][r] = v.x;
            As[kq * 4 + 1][r] = v.y;
            As[kq * 4 + 2][r] = v.z;
            As[kq * 4 + 3][r] = v.w;
        }
        {
            int k  = tid >> 4;
            int cq = tid & 15;
            *(float4*)&Bs[k][cq * 4] =
                *(const float4*)(W + (size_t)(kb + k) * Ncols + col0 + cq * 4);
        }
        __syncthreads();

        #pragma unroll
        for (int k = 0; k < 16; ++k) {
            ulonglong2 b2 = *(const ulonglong2*)&Bs[k][cg * 4];  // 2 col-pairs
            float4 a0 = *(const float4*)&As[k][rg * 8];
            float4 a1 = *(const float4*)&As[k][rg * 8 + 4];
            float a[8] = {a0.x, a0.y, a0.z, a0.w, a1.x, a1.y, a1.z, a1.w};
            #pragma unroll
            for (int i = 0; i < 8; ++i) {
                u64t as2 = splat2(a[i]);
                acc2[i][0] = ffma2(as2, b2.x, acc2[i][0]);
                acc2[i][1] = ffma2(as2, b2.y, acc2[i][1]);
            }
        }
    }

    float4 bv = *(const float4*)(bias + col0 + cg * 4);
    #pragma unroll
    for (int i = 0; i < 8; ++i) {
        int row = row0 + rg * 8 + i;
        float2 p0 = unpack2(acc2[i][0]);
        float2 p1 = unpack2(acc2[i][1]);
        float4 o;
        o.x = fmaxf(p0.x + bv.x, 0.f);
        o.y = fmaxf(p0.y + bv.y, 0.f);
        o.z = fmaxf(p1.x + bv.z, 0.f);
        o.w = fmaxf(p1.y + bv.w, 0.f);
        *(float4*)(Cout + (size_t)row * Ncols + col0 + cg * 4) = o;
    }
}

// All three projections in one launch.
// grid.x: 0 -> f (C=64), 1 -> g (C=64), 2..9 -> h column-blocks (F=512).
__global__ __launch_bounds__(256)
void proj_all_kernel(const float* __restrict__ A,
                     const float* __restrict__ Wf, const float* __restrict__ bf,
                     const float* __restrict__ Wg, const float* __restrict__ bg,
                     const float* __restrict__ Wh, const float* __restrict__ bh,
                     float* __restrict__ Fout, float* __restrict__ Gout,
                     float* __restrict__ Hout)
{
    const int cx   = blockIdx.x;
    const int row0 = blockIdx.y * 128;
    const float* W;  const float* bb;  float* C;  int Ncols;  int col0;
    if (cx == 0)      { W = Wf; bb = bf; C = Fout; Ncols = CDIM; col0 = 0; }
    else if (cx == 1) { W = Wg; bb = bg; C = Gout; Ncols = CDIM; col0 = 0; }
    else              { W = Wh; bb = bh; C = Hout; Ncols = FDIM; col0 = (cx - 2) * 64; }
    proj_body(A, W, bb, C, Ncols, row0, col0);
}

// ---------------------------------------------------------------------------
// Flash attention (fp32, packed f32x2). Per CTA: 32 query rows of one batch.
//   GEMM1 (QK^T) in registers packed along C; softmax fused in registers;
//   probabilities written duplicated ({p,p} u64) so GEMM2 reads splat
//   operands with LDS.128. GEMM2 packed along F, branch-free prefetch,
//   4-row chunks to bound live registers. Epilogue: out = gamma*(O/l) + V.
// ---------------------------------------------------------------------------
#define BM 32
#define BN 64

__global__ __launch_bounds__(256, 2)
void attn_kernel(const float* __restrict__ Qf, const float* __restrict__ Kg,
                 const float* __restrict__ Hh, const float* __restrict__ Vin,
                 const float* __restrict__ gamma, float* __restrict__ out)
{
    __shared__ float Qs[BM][CDIM + 4];      // 272B stride
    __shared__ float Ks[BN][CDIM];          // XOR-swizzled chunks, 256B stride
    __shared__ u64t  Pp[BN][BM + 2];        // {p,p} duplicated probs, 272B stride
    __shared__ float m_s[BM], l_s[BM], al_s[BM];
    __shared__ float gam_s[FDIM];

    const int tid  = threadIdx.x;
    const int b    = blockIdx.y;
    const int row0 = blockIdx.x * BM;

    // GEMM1 mapping: 2 rows x 4 cols per thread over S[32][64]
    const int r1  = (tid >> 4) * 2;
    const int c1  = (tid & 15) * 4;
    const int sw1 = tid & 15;               // Ks chunk swizzle key
    // GEMM2 mapping: 8 rows x 8 cols per thread
    const int r2 = (tid >> 6) * 8;
    const int c2 = (tid & 63) * 8;

    {
        const float* qp = Qf + ((size_t)b * NDIM + row0) * CDIM;
        for (int s = tid; s < BM * CDIM / 4; s += 256) {
            int r  = s >> 4;
            int k4 = s & 15;
            *(float4*)&Qs[r][k4 * 4] = *(const float4*)(qp + r * CDIM + k4 * 4);
        }
    }
    for (int s = tid; s < FDIM / 4; s += 256)
        *(float4*)&gam_s[s * 4] = *(const float4*)(gamma + s * 4);
    if (tid < BM) { m_s[tid] = -INFINITY; l_s[tid] = 0.f; }

    u64t acc2[8][4];                        // 4 col-pairs of 8 F-cols
    #pragma unroll
    for (int i = 0; i < 8; ++i)
        #pragma unroll
        for (int k = 0; k < 4; ++k) acc2[i][k] = 0ull;

    for (int jt = 0; jt < NDIM / BN; ++jt) {
        __syncthreads();   // prior GEMM2 done with Pp; Ks free
        {   // Load K tile (64x64) with XOR-swizzled 16B chunks
            const float* kp = Kg + ((size_t)b * NDIM + jt * BN) * CDIM;
            #pragma unroll
            for (int t = 0; t < 4; ++t) {
                int s  = tid + t * 256;
                int r  = s >> 4;
                int kc = s & 15;
                *(float4*)&Ks[r][((kc ^ ((r >> 2) & 15)) & 15) * 4] =
                    *(const float4*)(kp + r * CDIM + kc * 4);
            }
        }
        __syncthreads();

        // --- GEMM1: S = Q K^T packed along C; softmax in registers ---
        {
            u64t sa2[2][4];
            #pragma unroll
            for (int i = 0; i < 2; ++i)
                #pragma unroll
                for (int c = 0; c < 4; ++c) sa2[i][c] = 0ull;

            #pragma unroll
            for (int k4 = 0; k4 < CDIM / 4; ++k4) {
                ulonglong2 qa = *(const ulonglong2*)&Qs[r1][k4 * 4];
                ulonglong2 qb = *(const ulonglong2*)&Qs[r1 + 1][k4 * 4];
                #pragma unroll
                for (int c = 0; c < 4; ++c) {
                    ulonglong2 kv =
                        *(const ulonglong2*)&Ks[c1 + c][((k4 ^ sw1) & 15) * 4];
                    sa2[0][c] = ffma2(qa.x, kv.x, sa2[0][c]);
                    sa2[0][c] = ffma2(qa.y, kv.y, sa2[0][c]);
                    sa2[1][c] = ffma2(qb.x, kv.x, sa2[1][c]);
                    sa2[1][c] = ffma2(qb.y, kv.y, sa2[1][c]);
                }
            }
            float s0[4], s1[4];
            #pragma unroll
            for (int c = 0; c < 4; ++c) {
                float2 t0 = unpack2(sa2[0][c]); s0[c] = t0.x + t0.y;
                float2 t1 = unpack2(sa2[1][c]); s1[c] = t1.x + t1.y;
            }

            // Row reductions across the 16 lanes owning this row
            float mx0 = fmaxf(fmaxf(s0[0], s0[1]), fmaxf(s0[2], s0[3]));
            float mx1 = fmaxf(fmaxf(s1[0], s1[1]), fmaxf(s1[2], s1[3]));
            #pragma unroll
            for (int d = 1; d < 16; d <<= 1) {
                mx0 = fmaxf(mx0, __shfl_xor_sync(0xffffffffu, mx0, d));
                mx1 = fmaxf(mx1, __shfl_xor_sync(0xffffffffu, mx1, d));
            }
            float mold0 = m_s[r1], mold1 = m_s[r1 + 1];
            float mn0 = fmaxf(mold0, mx0), mn1 = fmaxf(mold1, mx1);
            float sum0 = 0.f, sum1 = 0.f;
            float p0[4], p1[4];
            #pragma unroll
            for (int c = 0; c < 4; ++c) {
                p0[c] = exp2f((s0[c] - mn0) * LOG2E); sum0 += p0[c];
                p1[c] = exp2f((s1[c] - mn1) * LOG2E); sum1 += p1[c];
            }
            #pragma unroll
            for (int d = 1; d < 16; d <<= 1) {
                sum0 += __shfl_xor_sync(0xffffffffu, sum0, d);
                sum1 += __shfl_xor_sync(0xffffffffu, sum1, d);
            }
            if ((tid & 15) == 0) {
                float a0 = exp2f((mold0 - mn0) * LOG2E);   // 0 on first tile
                float a1 = exp2f((mold1 - mn1) * LOG2E);
                m_s[r1]      = mn0;  m_s[r1 + 1]  = mn1;
                al_s[r1]     = a0;   al_s[r1 + 1] = a1;
                l_s[r1]      = l_s[r1] * a0 + sum0;
                l_s[r1 + 1]  = l_s[r1 + 1] * a1 + sum1;
            }
            // Duplicated-prob store: Pp[j][r] = {p,p}
            #pragma unroll
            for (int c = 0; c < 4; ++c) {
                Pp[c1 + c][r1]     = splat2(p0[c]);
                Pp[c1 + c][r1 + 1] = splat2(p1[c]);
            }
        }
        __syncthreads();

        // --- rescale + GEMM2: O += P * H (packed, chunked for reg budget) ---
        #pragma unroll
        for (int i = 0; i < 8; ++i) {
            u64t a2 = splat2(al_s[r2 + i]);
            acc2[i][0] = fmul2(acc2[i][0], a2);
            acc2[i][1] = fmul2(acc2[i][1], a2);
            acc2[i][2] = fmul2(acc2[i][2], a2);
            acc2[i][3] = fmul2(acc2[i][3], a2);
        }
        const float* hp = Hh + ((size_t)b * NDIM + (size_t)jt * BN) * FDIM + c2;
        ulonglong2 h0 = *(const ulonglong2*)(hp);
        ulonglong2 h1 = *(const ulonglong2*)(hp + 4);
        #pragma unroll 4
        for (int j = 0; j < BN; ++j) {
            // unconditional one-row-ahead prefetch (g_h padded: always legal)
            ulonglong2 n0 = *(const ulonglong2*)(hp + (size_t)(j + 1) * FDIM);
            ulonglong2 n1 = *(const ulonglong2*)(hp + (size_t)(j + 1) * FDIM + 4);
            {   // rows r2..r2+3: probs loaded just-in-time (caps live regs)
                ulonglong2 pa = *(const ulonglong2*)&Pp[j][r2];
                ulonglong2 pb = *(const ulonglong2*)&Pp[j][r2 + 2];
                acc2[0][0] = ffma2(pa.x, h0.x, acc2[0][0]);
                acc2[0][1] = ffma2(pa.x, h0.y, acc2[0][1]);
                acc2[0][2] = ffma2(pa.x, h1.x, acc2[0][2]);
                acc2[0][3] = ffma2(pa.x, h1.y, acc2[0][3]);
                acc2[1][0] = ffma2(pa.y, h0.x, acc2[1][0]);
                acc2[1][1] = ffma2(pa.y, h0.y, acc2[1][1]);
                acc2[1][2] = ffma2(pa.y, h1.x, acc2[1][2]);
                acc2[1][3] = ffma2(pa.y, h1.y, acc2[1][3]);
                acc2[2][0] = ffma2(pb.x, h0.x, acc2[2][0]);
                acc2[2][1] = ffma2(pb.x, h0.y, acc2[2][1]);
                acc2[2][2] = ffma2(pb.x, h1.x, acc2[2][2]);
                acc2[2][3] = ffma2(pb.x, h1.y, acc2[2][3]);
                acc2[3][0] = ffma2(pb.y, h0.x, acc2[3][0]);
                acc2[3][1] = ffma2(pb.y, h0.y, acc2[3][1]);
                acc2[3][2] = ffma2(pb.y, h1.x, acc2[3][2]);
                acc2[3][3] = ffma2(pb.y, h1.y, acc2[3][3]);
            }
            {   // rows r2+4..r2+7
                ulonglong2 pc = *(const ulonglong2*)&Pp[j][r2 + 4];
                ulonglong2 pd = *(const ulonglong2*)&Pp[j][r2 + 6];
                acc2[4][0] = ffma2(pc.x, h0.x, acc2[4][0]);
                acc2[4][1] = ffma2(pc.x, h0.y, acc2[4][1]);
                acc2[4][2] = ffma2(pc.x, h1.x, acc2[4][2]);
                acc2[4][3] = ffma2(pc.x, h1.y, acc2[4][3]);
                acc2[5][0] = ffma2(pc.y, h0.x, acc2[5][0]);
                acc2[5][1] = ffma2(pc.y, h0.y, acc2[5][1]);
                acc2[5][2] = ffma2(pc.y, h1.x, acc2[5][2]);
                acc2[5][3] = ffma2(pc.y, h1.y, acc2[5][3]);
                acc2[6][0] = ffma2(pd.x, h0.x, acc2[6][0]);
                acc2[6][1] = ffma2(pd.x, h0.y, acc2[6][1]);
                acc2[6][2] = ffma2(pd.x, h1.x, acc2[6][2]);
                acc2[6][3] = ffma2(pd.x, h1.y, acc2[6][3]);
                acc2[7][0] = ffma2(pd.y, h0.x, acc2[7][0]);
                acc2[7][1] = ffma2(pd.y, h0.y, acc2[7][1]);
                acc2[7][2] = ffma2(pd.y, h1.x, acc2[7][2]);
                acc2[7][3] = ffma2(pd.y, h1.y, acc2[7][3]);
            }
            h0 = n0; h1 = n1;
        }
    }

    // --- epilogue: out = gamma * (O/l) + V ---
    #pragma unroll
    for (int i = 0; i < 8; ++i) {
        float inv = 1.f / l_s[r2 + i];
        size_t base = ((size_t)b * NDIM + row0 + r2 + i) * FDIM + c2;
        float4 v0 = *(const float4*)(Vin + base);
        float4 v1 = *(const float4*)(Vin + base + 4);
        float2 q0 = unpack2(acc2[i][0]);
        float2 q1 = unpack2(acc2[i][1]);
        float2 q2 = unpack2(acc2[i][2]);
        float2 q3 = unpack2(acc2[i][3]);
        float4 o0, o1;
        o0.x = gam_s[c2 + 0] * (q0.x * inv) + v0.x;
        o0.y = gam_s[c2 + 1] * (q0.y * inv) + v0.y;
        o0.z = gam_s[c2 + 2] * (q1.x * inv) + v0.z;
        o0.w = gam_s[c2 + 3] * (q1.y * inv) + v0.w;
        o1.x = gam_s[c2 + 4] * (q2.x * inv) + v1.x;
        o1.y = gam_s[c2 + 5] * (q2.y * inv) + v1.y;
        o1.z = gam_s[c2 + 6] * (q3.x * inv) + v1.z;
        o1.w = gam_s[c2 + 7] * (q3.y * inv) + v1.w;
        *(float4*)(out + base)     = o0;
        *(float4*)(out + base + 4) = o1;
    }
}

// ---------------------------------------------------------------------------
extern "C" void kernel_launch(void* const* d_in, const int* in_sizes, int n_in,
                              void* d_out, int out_size)
{
    const float* V     = (const float*)d_in[0];
    const float* Wf    = (const float*)d_in[1];
    const float* bf    = (const float*)d_in[2];
    const float* Wg    = (const float*)d_in[3];
    const float* bg    = (const float*)d_in[4];
    const float* Wh    = (const float*)d_in[5];
    const float* bh    = (const float*)d_in[6];
    const float* gamma = (const float*)d_in[7];
    float* outp = (float*)d_out;

    float *fp, *gp, *hp;
    cudaGetSymbolAddress((void**)&fp, g_f);
    cudaGetSymbolAddress((void**)&gp, g_g);
    cudaGetSymbolAddress((void**)&hp, g_h);

    dim3 thr(256);
    proj_all_kernel<<<dim3(10, MROWS / 128), thr>>>(V, Wf, bf, Wg, bg, Wh, bh,
                                                    fp, gp, hp);
    attn_kernel<<<dim3(NDIM / BM, BDIM), thr>>>(fp, gp, hp, V, gamma, outp);
}

// round 14
// speedup vs baseline: 1.0985x; 1.0985x over previous
#include <cuda_runtime.h>
#include <cuda_bf16.h>
#include <math.h>

// ---------------------------------------------------------------------------
// NodeSelfAtten: B=4, N=4096, F=512, C=64
// Round 14: round-11 l1tex fix still unmeasured (three broker timeouts).
// Measured baseline (round 10): 2539us, fma 37.5%, L1 63.5% -> l1tex-bound.
// Fix in flight: GEMM2 ROW-PAIR packed — probs read non-duplicated (2x
// LDS.128/j instead of 4x splatted), H splatted in-register on idle alu pipe.
// Predicted: 1800-2100us.
// ---------------------------------------------------------------------------

#define BDIM   4
#define NDIM   4096
#define FDIM   512
#define CDIM   64
#define MROWS  (BDIM * NDIM)        // 16384
#define LOG2E  1.4426950408889634f

typedef unsigned long long u64t;

__device__ __forceinline__ u64t ffma2(u64t a, u64t b, u64t c) {
    u64t d;
    asm("fma.rn.f32x2 %0, %1, %2, %3;" : "=l"(d) : "l"(a), "l"(b), "l"(c));
    return d;
}
__device__ __forceinline__ u64t fmul2(u64t a, u64t b) {
    u64t d;
    asm("mul.rn.f32x2 %0, %1, %2;" : "=l"(d) : "l"(a), "l"(b));
    return d;
}
__device__ __forceinline__ u64t splat2(float x) {
    u64t d;
    asm("mov.b64 %0, {%1, %1};" : "=l"(d) : "f"(x));
    return d;
}
__device__ __forceinline__ float2 unpack2(u64t v) {
    float lo, hi;
    asm("mov.b64 {%0, %1}, %2;" : "=f"(lo), "=f"(hi) : "l"(v));
    return make_float2(lo, hi);
}

// Scratch (device globals). g_h padded so prefetch of row j+1 is always legal.
__device__ float g_f[BDIM * NDIM * CDIM];          // 4 MB
__device__ float g_g[BDIM * NDIM * CDIM];          // 4 MB
__device__ float g_h[BDIM * NDIM * FDIM + 1024];   // 32 MB + pad

// ---------------------------------------------------------------------------
// Projection GEMM body (unchanged — projection phase measured small).
// ---------------------------------------------------------------------------
__device__ __forceinline__
void proj_body(const float* __restrict__ A, const float* __restrict__ W,
               const float* __restrict__ bias, float* __restrict__ Cout,
               int Ncols, int row0, int col0)
{
    __shared__ float As[16][132];
    __shared__ float Bs[16][68];

    const int tid = threadIdx.x;
    const int rg  = tid >> 4;
    const int cg  = tid & 15;

    u64t acc2[8][2];
    #pragma unroll
    for (int i = 0; i < 8; ++i) { acc2[i][0] = 0ull; acc2[i][1] = 0ull; }

    for (int kb = 0; kb < 512; kb += 16) {
        __syncthreads();
        #pragma unroll
        for (int t = 0; t < 2; ++t) {
            int s  = tid + t * 256;
            int r  = s >> 2;
            int kq = s & 3;
            float4 v = *(const float4*)(A + (size_t)(row0 + r) * 512 + kb + kq * 4);
            As[kq * 4 + 0][r] = v.x;
            As[kq * 4 + 1][r] = v.y;
            As[kq * 4 + 2][r] = v.z;
            As[kq * 4 + 3][r] = v.w;
        }
        {
            int k  = tid >> 4;
            int cq = tid & 15;
            *(float4*)&Bs[k][cq * 4] =
                *(const float4*)(W + (size_t)(kb + k) * Ncols + col0 + cq * 4);
        }
        __syncthreads();

        #pragma unroll
        for (int k = 0; k < 16; ++k) {
            ulonglong2 b2 = *(const ulonglong2*)&Bs[k][cg * 4];
            float4 a0 = *(const float4*)&As[k][rg * 8];
            float4 a1 = *(const float4*)&As[k][rg * 8 + 4];
            float a[8] = {a0.x, a0.y, a0.z, a0.w, a1.x, a1.y, a1.z, a1.w};
            #pragma unroll
            for (int i = 0; i < 8; ++i) {
                u64t as2 = splat2(a[i]);
                acc2[i][0] = ffma2(as2, b2.x, acc2[i][0]);
                acc2[i][1] = ffma2(as2, b2.y, acc2[i][1]);
            }
        }
    }

    float4 bv = *(const float4*)(bias + col0 + cg * 4);
    #pragma unroll
    for (int i = 0; i < 8; ++i) {
        int row = row0 + rg * 8 + i;
        float2 p0 = unpack2(acc2[i][0]);
        float2 p1 = unpack2(acc2[i][1]);
        float4 o;
        o.x = fmaxf(p0.x + bv.x, 0.f);
        o.y = fmaxf(p0.y + bv.y, 0.f);
        o.z = fmaxf(p1.x + bv.z, 0.f);
        o.w = fmaxf(p1.y + bv.w, 0.f);
        *(float4*)(Cout + (size_t)row * Ncols + col0 + cg * 4) = o;
    }
}

__global__ __launch_bounds__(256)
void proj_all_kernel(const float* __restrict__ A,
                     const float* __restrict__ Wf, const float* __restrict__ bf,
                     const float* __restrict__ Wg, const float* __restrict__ bg,
                     const float* __restrict__ Wh, const float* __restrict__ bh,
                     float* __restrict__ Fout, float* __restrict__ Gout,
                     float* __restrict__ Hout)
{
    const int cx   = blockIdx.x;
    const int row0 = blockIdx.y * 128;
    const float* W;  const float* bb;  float* C;  int Ncols;  int col0;
    if (cx == 0)      { W = Wf; bb = bf; C = Fout; Ncols = CDIM; col0 = 0; }
    else if (cx == 1) { W = Wg; bb = bg; C = Gout; Ncols = CDIM; col0 = 0; }
    else              { W = Wh; bb = bh; C = Hout; Ncols = FDIM; col0 = (cx - 2) * 64; }
    proj_body(A, W, bb, C, Ncols, row0, col0);
}

// ---------------------------------------------------------------------------
// Flash attention. GEMM2 ROW-PAIR packed:
//   acc2[rp][c] = {O[r2+2rp][c2+c], O[r2+2rp+1][c2+c]}
//   probs read non-duplicated from PsT (2x LDS.128/j); H splatted in-register.
// ---------------------------------------------------------------------------
#define BM 32
#define BN 64

__global__ __launch_bounds__(256, 2)
void attn_kernel(const float* __restrict__ Qf, const float* __restrict__ Kg,
                 const float* __restrict__ Hh, const float* __restrict__ Vin,
                 const float* __restrict__ gamma, float* __restrict__ out)
{
    __shared__ float Qs[BM][CDIM + 4];      // 272B stride
    __shared__ float Ks[BN][CDIM];          // XOR-swizzled chunks
    __shared__ float PsT[BN][BM + 4];       // transposed probs, 144B stride
    __shared__ float m_s[BM], l_s[BM], al_s[BM];
    __shared__ float gam_s[FDIM];

    const int tid  = threadIdx.x;
    const int b    = blockIdx.y;
    const int row0 = blockIdx.x * BM;

    const int r1  = (tid >> 4) * 2;         // GEMM1: rows r1, r1+1
    const int c1  = (tid & 15) * 4;         // GEMM1: cols c1..c1+3
    const int sw1 = tid & 15;
    const int r2 = (tid >> 6) * 8;          // GEMM2: rows r2..r2+7 (4 pairs)
    const int c2 = (tid & 63) * 8;          // GEMM2: cols c2..c2+7

    {
        const float* qp = Qf + ((size_t)b * NDIM + row0) * CDIM;
        for (int s = tid; s < BM * CDIM / 4; s += 256) {
            int r  = s >> 4;
            int k4 = s & 15;
            *(float4*)&Qs[r][k4 * 4] = *(const float4*)(qp + r * CDIM + k4 * 4);
        }
    }
    for (int s = tid; s < FDIM / 4; s += 256)
        *(float4*)&gam_s[s * 4] = *(const float4*)(gamma + s * 4);
    if (tid < BM) { m_s[tid] = -INFINITY; l_s[tid] = 0.f; }

    u64t acc2[4][8];                        // [row-pair][col]
    #pragma unroll
    for (int rp = 0; rp < 4; ++rp)
        #pragma unroll
        for (int c = 0; c < 8; ++c) acc2[rp][c] = 0ull;

    for (int jt = 0; jt < NDIM / BN; ++jt) {
        __syncthreads();
        {   // K tile load (XOR-swizzled 16B chunks)
            const float* kp = Kg + ((size_t)b * NDIM + jt * BN) * CDIM;
            #pragma unroll
            for (int t = 0; t < 4; ++t) {
                int s  = tid + t * 256;
                int r  = s >> 4;
                int kc = s & 15;
                *(float4*)&Ks[r][((kc ^ ((r >> 2) & 15)) & 15) * 4] =
                    *(const float4*)(kp + r * CDIM + kc * 4);
            }
        }
        __syncthreads();

        // --- GEMM1 + softmax (probs stored transposed, NON-duplicated) ---
        {
            u64t sa2[2][4];
            #pragma unroll
            for (int i = 0; i < 2; ++i)
                #pragma unroll
                for (int c = 0; c < 4; ++c) sa2[i][c] = 0ull;

            #pragma unroll
            for (int k4 = 0; k4 < CDIM / 4; ++k4) {
                ulonglong2 qa = *(const ulonglong2*)&Qs[r1][k4 * 4];
                ulonglong2 qb = *(const ulonglong2*)&Qs[r1 + 1][k4 * 4];
                #pragma unroll
                for (int c = 0; c < 4; ++c) {
                    ulonglong2 kv =
                        *(const ulonglong2*)&Ks[c1 + c][((k4 ^ sw1) & 15) * 4];
                    sa2[0][c] = ffma2(qa.x, kv.x, sa2[0][c]);
                    sa2[0][c] = ffma2(qa.y, kv.y, sa2[0][c]);
                    sa2[1][c] = ffma2(qb.x, kv.x, sa2[1][c]);
                    sa2[1][c] = ffma2(qb.y, kv.y, sa2[1][c]);
                }
            }
            float s0[4], s1[4];
            #pragma unroll
            for (int c = 0; c < 4; ++c) {
                float2 t0 = unpack2(sa2[0][c]); s0[c] = t0.x + t0.y;
                float2 t1 = unpack2(sa2[1][c]); s1[c] = t1.x + t1.y;
            }

            float mx0 = fmaxf(fmaxf(s0[0], s0[1]), fmaxf(s0[2], s0[3]));
            float mx1 = fmaxf(fmaxf(s1[0], s1[1]), fmaxf(s1[2], s1[3]));
            #pragma unroll
            for (int d = 1; d < 16; d <<= 1) {
                mx0 = fmaxf(mx0, __shfl_xor_sync(0xffffffffu, mx0, d));
                mx1 = fmaxf(mx1, __shfl_xor_sync(0xffffffffu, mx1, d));
            }
            float mold0 = m_s[r1], mold1 = m_s[r1 + 1];
            float mn0 = fmaxf(mold0, mx0), mn1 = fmaxf(mold1, mx1);
            float sum0 = 0.f, sum1 = 0.f;
            float p0[4], p1[4];
            #pragma unroll
            for (int c = 0; c < 4; ++c) {
                p0[c] = exp2f((s0[c] - mn0) * LOG2E); sum0 += p0[c];
                p1[c] = exp2f((s1[c] - mn1) * LOG2E); sum1 += p1[c];
            }
            #pragma unroll
            for (int d = 1; d < 16; d <<= 1) {
                sum0 += __shfl_xor_sync(0xffffffffu, sum0, d);
                sum1 += __shfl_xor_sync(0xffffffffu, sum1, d);
            }
            if ((tid & 15) == 0) {
                float a0 = exp2f((mold0 - mn0) * LOG2E);   // 0 on first tile
                float a1 = exp2f((mold1 - mn1) * LOG2E);
                m_s[r1]      = mn0;  m_s[r1 + 1]  = mn1;
                al_s[r1]     = a0;   al_s[r1 + 1] = a1;
                l_s[r1]      = l_s[r1] * a0 + sum0;
                l_s[r1 + 1]  = l_s[r1 + 1] * a1 + sum1;
            }
            // Plain transposed store: rows r1,r1+1 contiguous -> float2
            #pragma unroll
            for (int c = 0; c < 4; ++c)
                *(float2*)&PsT[c1 + c][r1] = make_float2(p0[c], p1[c]);
        }
        __syncthreads();

        // --- rescale: alpha pairs come straight from al_s as LDS.64 ---
        #pragma unroll
        for (int rp = 0; rp < 4; ++rp) {
            u64t apair = *(const u64t*)&al_s[r2 + 2 * rp];   // {a_r, a_r+1}
            #pragma unroll
            for (int c = 0; c < 8; ++c) acc2[rp][c] = fmul2(acc2[rp][c], apair);
        }

        // --- GEMM2: O += P * H, row-pair packed ---
        const float* hp = Hh + ((size_t)b * NDIM + (size_t)jt * BN) * FDIM + c2;
        float4 f0 = *(const float4*)(hp);
        float4 f1 = *(const float4*)(hp + 4);
        #pragma unroll 4
        for (int j = 0; j < BN; ++j) {
            // prefetch next H row (g_h padded: always legal)
            float4 g0 = *(const float4*)(hp + (size_t)(j + 1) * FDIM);
            float4 g1 = *(const float4*)(hp + (size_t)(j + 1) * FDIM + 4);
            // 8 probs = 4 natural row-pairs via 2 broadcast LDS.128
            ulonglong2 pa = *(const ulonglong2*)&PsT[j][r2];       // pairs 0,1
            ulonglong2 pb = *(const ulonglong2*)&PsT[j][r2 + 4];   // pairs 2,3
            {   // cols 0..3 (splats JIT to cap live regs)
                u64t h0 = splat2(f0.x), h1 = splat2(f0.y);
                u64t h2 = splat2(f0.z), h3 = splat2(f0.w);
                acc2[0][0] = ffma2(pa.x, h0, acc2[0][0]);
                acc2[1][0] = ffma2(pa.y, h0, acc2[1][0]);
                acc2[2][0] = ffma2(pb.x, h0, acc2[2][0]);
                acc2[3][0] = ffma2(pb.y, h0, acc2[3][0]);
                acc2[0][1] = ffma2(pa.x, h1, acc2[0][1]);
                acc2[1][1] = ffma2(pa.y, h1, acc2[1][1]);
                acc2[2][1] = ffma2(pb.x, h1, acc2[2][1]);
                acc2[3][1] = ffma2(pb.y, h1, acc2[3][1]);
                acc2[0][2] = ffma2(pa.x, h2, acc2[0][2]);
                acc2[1][2] = ffma2(pa.y, h2, acc2[1][2]);
                acc2[2][2] = ffma2(pb.x, h2, acc2[2][2]);
                acc2[3][2] = ffma2(pb.y, h2, acc2[3][2]);
                acc2[0][3] = ffma2(pa.x, h3, acc2[0][3]);
                acc2[1][3] = ffma2(pa.y, h3, acc2[1][3]);
                acc2[2][3] = ffma2(pb.x, h3, acc2[2][3]);
                acc2[3][3] = ffma2(pb.y, h3, acc2[3][3]);
            }
            {   // cols 4..7
                u64t h4 = splat2(f1.x), h5 = splat2(f1.y);
                u64t h6 = splat2(f1.z), h7 = splat2(f1.w);
                acc2[0][4] = ffma2(pa.x, h4, acc2[0][4]);
                acc2[1][4] = ffma2(pa.y, h4, acc2[1][4]);
                acc2[2][4] = ffma2(pb.x, h4, acc2[2][4]);
                acc2[3][4] = ffma2(pb.y, h4, acc2[3][4]);
                acc2[0][5] = ffma2(pa.x, h5, acc2[0][5]);
                acc2[1][5] = ffma2(pa.y, h5, acc2[1][5]);
                acc2[2][5] = ffma2(pb.x, h5, acc2[2][5]);
                acc2[3][5] = ffma2(pb.y, h5, acc2[3][5]);
                acc2[0][6] = ffma2(pa.x, h6, acc2[0][6]);
                acc2[1][6] = ffma2(pa.y, h6, acc2[1][6]);
                acc2[2][6] = ffma2(pb.x, h6, acc2[2][6]);
                acc2[3][6] = ffma2(pb.y, h6, acc2[3][6]);
                acc2[0][7] = ffma2(pa.x, h7, acc2[0][7]);
                acc2[1][7] = ffma2(pa.y, h7, acc2[1][7]);
                acc2[2][7] = ffma2(pb.x, h7, acc2[2][7]);
                acc2[3][7] = ffma2(pb.y, h7, acc2[3][7]);
            }
            f0 = g0; f1 = g1;
        }
    }

    // --- epilogue: out = gamma * (O/l) + V, two rows per pair ---
    #pragma unroll
    for (int rp = 0; rp < 4; ++rp) {
        int rowa = r2 + 2 * rp;
        float inva = 1.f / l_s[rowa];
        float invb = 1.f / l_s[rowa + 1];
        float2 u[8];
        #pragma unroll
        for (int c = 0; c < 8; ++c) u[c] = unpack2(acc2[rp][c]);

        size_t basea = ((size_t)b * NDIM + row0 + rowa) * FDIM + c2;
        size_t baseb = basea + FDIM;
        float4 va0 = *(const float4*)(Vin + basea);
        float4 va1 = *(const float4*)(Vin + basea + 4);
        float4 vb0 = *(const float4*)(Vin + baseb);
        float4 vb1 = *(const float4*)(Vin + baseb + 4);
        float4 oa0, oa1, ob0, ob1;
        oa0.x = gam_s[c2 + 0] * (u[0].x * inva) + va0.x;
        oa0.y = gam_s[c2 + 1] * (u[1].x * inva) + va0.y;
        oa0.z = gam_s[c2 + 2] * (u[2].x * inva) + va0.z;
        oa0.w = gam_s[c2 + 3] * (u[3].x * inva) + va0.w;
        oa1.x = gam_s[c2 + 4] * (u[4].x * inva) + va1.x;
        oa1.y = gam_s[c2 + 5] * (u[5].x * inva) + va1.y;
        oa1.z = gam_s[c2 + 6] * (u[6].x * inva) + va1.z;
        oa1.w = gam_s[c2 + 7] * (u[7].x * inva) + va1.w;
        ob0.x = gam_s[c2 + 0] * (u[0].y * invb) + vb0.x;
        ob0.y = gam_s[c2 + 1] * (u[1].y * invb) + vb0.y;
        ob0.z = gam_s[c2 + 2] * (u[2].y * invb) + vb0.z;
        ob0.w = gam_s[c2 + 3] * (u[3].y * invb) + vb0.w;
        ob1.x = gam_s[c2 + 4] * (u[4].y * invb) + vb1.x;
        ob1.y = gam_s[c2 + 5] * (u[5].y * invb) + vb1.y;
        ob1.z = gam_s[c2 + 6] * (u[6].y * invb) + vb1.z;
        ob1.w = gam_s[c2 + 7] * (u[7].y * invb) + vb1.w;
        *(float4*)(out + basea)     = oa0;
        *(float4*)(out + basea + 4) = oa1;
        *(float4*)(out + baseb)     = ob0;
        *(float4*)(out + baseb + 4) = ob1;
    }
}

// ---------------------------------------------------------------------------
extern "C" void kernel_launch(void* const* d_in, const int* in_sizes, int n_in,
                              void* d_out, int out_size)
{
    const float* V     = (const float*)d_in[0];
    const float* Wf    = (const float*)d_in[1];
    const float* bf    = (const float*)d_in[2];
    const float* Wg    = (const float*)d_in[3];
    const float* bg    = (const float*)d_in[4];
    const float* Wh    = (const float*)d_in[5];
    const float* bh    = (const float*)d_in[6];
    const float* gamma = (const float*)d_in[7];
    float* outp = (float*)d_out;

    float *fp, *gp, *hp;
    cudaGetSymbolAddress((void**)&fp, g_f);
    cudaGetSymbolAddress((void**)&gp, g_g);
    cudaGetSymbolAddress((void**)&hp, g_h);

    dim3 thr(256);
    proj_all_kernel<<<dim3(10, MROWS / 128), thr>>>(V, Wf, bf, Wg, bg, Wh, bh,
                                                    fp, gp, hp);
    attn_kernel<<<dim3(NDIM / BM, BDIM), thr>>>(fp, gp, hp, V, gamma, outp);
}